// round 2
// baseline (speedup 1.0000x reference)
#include <cuda_runtime.h>
#include <math.h>

#define BB 64
#define WW 4096
#define HH 128
#define WC 256
#define CHUNKS 16   // WW / WC

// Scratch for attention partials (allocation-free: __device__ globals)
__device__ float g_m[BB * CHUNKS];
__device__ float g_s[BB * CHUNKS];
__device__ float g_acc[BB * CHUNKS * HH];

// ---------------------------------------------------------------------------
// Kernel 1: per-(batch, chunk) partial attention with online-softmax partials.
// One CTA = one 256-weight-index chunk of one batch. Stages 257 rows of
// encoder_output in SMEM (scores need row w-1, acc needs row w).
// ---------------------------------------------------------------------------
__global__ __launch_bounds__(256) void attn_partial(
    const float* __restrict__ enc,   // (B, W, H)
    const float* __restrict__ h0,    // (2, B, H)
    const float* __restrict__ c0,    // (2, B, H)
    const float* __restrict__ attW,  // (1, 2H)
    const float* __restrict__ attb)  // (1,)
{
    extern __shared__ float sm[];
    float* enc_s = sm;                   // (WC+1) * HH floats
    float* sc    = sm + (WC + 1) * HH;   // WC+1 scores / probs (padded to 260)
    float* red   = sc + 260;             // 8-entry reduce scratch

    const int b = blockIdx.y, c = blockIdx.x;
    const int t = threadIdx.x, lane = t & 31, wrp = t >> 5;

    // ---- scalar bias term: att_state[b] . wa_st + att_b ----
    float tb = 0.f;
    if (t < HH) {
        float hv = h0[(BB + b) * HH + t];   // layer 1 (last)
        float cv = c0[(BB + b) * HH + t];
        tb = hv * cv * attW[HH + t];
    }
    #pragma unroll
    for (int o = 16; o > 0; o >>= 1) tb += __shfl_xor_sync(0xffffffffu, tb, o);
    if (lane == 0) red[wrp] = tb;
    __syncthreads();
    float tbias = attb[0];
    #pragma unroll
    for (int g = 0; g < 8; ++g) tbias += red[g];
    __syncthreads();

    // wa_enc held per-lane as float4 (lane l owns cols 4l..4l+3)
    const float4 wa = reinterpret_cast<const float4*>(attW)[lane];

    const int r0 = c * WC;
    const float4* encv = reinterpret_cast<const float4*>(enc) + (long)b * WW * 32;

    // ---- phase A: warp-per-row load to SMEM + score during load ----
    for (int j = wrp; j <= WC; j += 8) {
        const int row = r0 - 1 + j;         // global row index; -1 only at c==0,j==0
        float4 v = make_float4(0.f, 0.f, 0.f, 0.f);
        if (row >= 0) v = encv[(long)row * 32 + lane];
        reinterpret_cast<float4*>(enc_s + j * HH)[lane] = v;
        float d = v.x * wa.x + v.y * wa.y + v.z * wa.z + v.w * wa.w;
        #pragma unroll
        for (int o = 16; o > 0; o >>= 1) d += __shfl_xor_sync(0xffffffffu, d, o);
        if (lane == 0) sc[j] = d + tbias;
    }
    __syncthreads();

    // ---- local softmax over the 256 logits of this chunk ----
    // weight index w = r0 + t uses score of row w-1 (= sc[t]); w==0 -> logit 0
    float l = sc[t];
    if (r0 + t == 0) l = 0.f;

    float m = l;
    #pragma unroll
    for (int o = 16; o > 0; o >>= 1) m = fmaxf(m, __shfl_xor_sync(0xffffffffu, m, o));
    if (lane == 0) red[wrp] = m;
    __syncthreads();
    float M = red[0];
    #pragma unroll
    for (int g = 1; g < 8; ++g) M = fmaxf(M, red[g]);
    __syncthreads();                       // red reads done before reuse

    float p = __expf(l - M);
    sc[t] = p;                             // each thread owns its own slot
    float s = p;
    #pragma unroll
    for (int o = 16; o > 0; o >>= 1) s += __shfl_xor_sync(0xffffffffu, s, o);
    if (lane == 0) red[wrp] = s;
    __syncthreads();                       // also publishes sc[] = p
    float S = 0.f;
    #pragma unroll
    for (int g = 0; g < 8; ++g) S += red[g];

    // ---- phase B: acc[h] = sum_i p[i] * enc[row r0+i][h]  (shared row i+1) ----
    // warp 'wrp' handles rows wrp*32..wrp*32+31; lane = float4 column (conflict-free)
    float4 acc = make_float4(0.f, 0.f, 0.f, 0.f);
    const float4* es = reinterpret_cast<const float4*>(enc_s);
    #pragma unroll 8
    for (int i = wrp * 32; i < wrp * 32 + 32; ++i) {
        float pv = sc[i];                  // broadcast within warp
        float4 e = es[(i + 1) * 32 + lane];
        acc.x += pv * e.x; acc.y += pv * e.y; acc.z += pv * e.z; acc.w += pv * e.w;
    }
    __syncthreads();                       // all enc_s reads done -> reuse as scratch
    float4* rbuf = reinterpret_cast<float4*>(enc_s);
    rbuf[wrp * 32 + lane] = acc;
    __syncthreads();
    if (wrp == 0) {
        float4 a = rbuf[lane];
        #pragma unroll
        for (int g = 1; g < 8; ++g) {
            float4 e = rbuf[g * 32 + lane];
            a.x += e.x; a.y += e.y; a.z += e.z; a.w += e.w;
        }
        reinterpret_cast<float4*>(g_acc + (b * CHUNKS + c) * HH)[lane] = a;
    }
    if (t == 0) { g_m[b * CHUNKS + c] = M; g_s[b * CHUNKS + c] = S; }
}

// ---------------------------------------------------------------------------
// Kernel 2: combine partials -> context x; input projection; 2 LSTM cells.
// One CTA per batch element, 512 threads (one per gate in the LSTM matmuls).
// ---------------------------------------------------------------------------
__device__ __forceinline__ float sigmoidf_(float v) {
    return 1.0f / (1.0f + __expf(-v));
}

__global__ __launch_bounds__(512) void decode_tail(
    const float* __restrict__ input,  // (B, 1, I)
    const float* __restrict__ h0,     // (2, B, H)
    const float* __restrict__ c0,     // (2, B, H)
    const float* __restrict__ inpW,   // (I, 2H)
    const float* __restrict__ inpb,   // (I,)
    const float* __restrict__ Wih0, const float* __restrict__ Whh0,
    const float* __restrict__ bih0, const float* __restrict__ bhh0,
    const float* __restrict__ Wih1, const float* __restrict__ Whh1,
    const float* __restrict__ bih1, const float* __restrict__ bhh1,
    float* __restrict__ out)          // [output(B,1,H) | h(2,B,H) | c(2,B,H)]
{
    __shared__ float x[HH], xin[HH], hh[HH], gates[4 * HH];
    const int b = blockIdx.x, t = threadIdx.x;

    // ---- combine chunk partials (log-sum-exp merge) ----
    if (t < HH) {
        float M = -INFINITY;
        #pragma unroll
        for (int c = 0; c < CHUNKS; ++c) M = fmaxf(M, g_m[b * CHUNKS + c]);
        float S = 0.f, a = 0.f;
        #pragma unroll
        for (int c = 0; c < CHUNKS; ++c) {
            float e = __expf(g_m[b * CHUNKS + c] - M);
            S += g_s[b * CHUNKS + c] * e;
            a += g_acc[(b * CHUNKS + c) * HH + t] * e;
        }
        x[t] = a / S;
    }
    __syncthreads();

    // ---- xin = [x, input] @ inp_W.T + inp_b ----
    if (t < HH) {
        const float* wrow = inpW + t * (2 * HH);
        const float* inb  = input + b * HH;
        float acc = inpb[t];
        #pragma unroll 8
        for (int k = 0; k < HH; ++k) acc += x[k] * wrow[k];
        #pragma unroll 8
        for (int k = 0; k < HH; ++k) acc += inb[k] * wrow[HH + k];
        xin[t] = acc;
        hh[t] = h0[b * HH + t];           // layer 0 hidden
    }
    __syncthreads();

    // ---- LSTM cell 0: 512 gates ----
    {
        const float* wi = Wih0 + t * HH;
        const float* wh = Whh0 + t * HH;
        float acc = bih0[t] + bhh0[t];
        #pragma unroll 8
        for (int k = 0; k < HH; ++k) acc += xin[k] * wi[k] + hh[k] * wh[k];
        gates[t] = acc;
    }
    __syncthreads();
    if (t < HH) {
        float ig = sigmoidf_(gates[t]);
        float fg = sigmoidf_(gates[HH + t]);
        float gg = tanhf(gates[2 * HH + t]);
        float og = sigmoidf_(gates[3 * HH + t]);
        float cn = fg * c0[b * HH + t] + ig * gg;
        float hn = og * tanhf(cn);
        xin[t] = hn;                                  // input to layer 1
        hh[t]  = h0[BB * HH + b * HH + t];            // layer 1 hidden
        out[8192 + b * HH + t] = hn;                  // h stack, layer 0
        out[8192 + 2 * BB * HH + b * HH + t] = cn;    // c stack, layer 0
    }
    __syncthreads();

    // ---- LSTM cell 1 ----
    {
        const float* wi = Wih1 + t * HH;
        const float* wh = Whh1 + t * HH;
        float acc = bih1[t] + bhh1[t];
        #pragma unroll 8
        for (int k = 0; k < HH; ++k) acc += xin[k] * wi[k] + hh[k] * wh[k];
        gates[t] = acc;
    }
    __syncthreads();
    if (t < HH) {
        float ig = sigmoidf_(gates[t]);
        float fg = sigmoidf_(gates[HH + t]);
        float gg = tanhf(gates[2 * HH + t]);
        float og = sigmoidf_(gates[3 * HH + t]);
        float cn = fg * c0[BB * HH + b * HH + t] + ig * gg;
        float hn = og * tanhf(cn);
        out[b * HH + t] = hn;                                   // output (B,1,H)
        out[8192 + BB * HH + b * HH + t] = hn;                  // h stack, layer 1
        out[8192 + 2 * BB * HH + BB * HH + b * HH + t] = cn;    // c stack, layer 1
    }
}

// ---------------------------------------------------------------------------
extern "C" void kernel_launch(void* const* d_in, const int* in_sizes, int n_in,
                              void* d_out, int out_size) {
    const float* input = (const float*)d_in[0];
    const float* h0    = (const float*)d_in[1];
    const float* c0    = (const float*)d_in[2];
    const float* enc   = (const float*)d_in[3];
    const float* attW  = (const float*)d_in[4];
    const float* attb  = (const float*)d_in[5];
    const float* inpW  = (const float*)d_in[6];
    const float* inpb  = (const float*)d_in[7];
    const float* Wih0  = (const float*)d_in[8];
    const float* Whh0  = (const float*)d_in[9];
    const float* bih0  = (const float*)d_in[10];
    const float* bhh0  = (const float*)d_in[11];
    const float* Wih1  = (const float*)d_in[12];
    const float* Whh1  = (const float*)d_in[13];
    const float* bih1  = (const float*)d_in[14];
    const float* bhh1  = (const float*)d_in[15];
    float* out = (float*)d_out;

    const int smem = ((WC + 1) * HH + 260 + 64) * (int)sizeof(float);  // ~132.9 KB
    cudaFuncSetAttribute(attn_partial, cudaFuncAttributeMaxDynamicSharedMemorySize, smem);

    attn_partial<<<dim3(CHUNKS, BB), 256, smem>>>(enc, h0, c0, attW, attb);
    decode_tail<<<BB, 512>>>(input, h0, c0, inpW, inpb,
                             Wih0, Whh0, bih0, bhh0,
                             Wih1, Whh1, bih1, bhh1, out);
}

// round 5
// speedup vs baseline: 4.2972x; 4.2972x over previous
#include <cuda_runtime.h>
#include <math.h>

#define BB 64
#define WW 4096
#define HH 128
#define WC 256
#define CHUNKS 16   // WW / WC
#define NT 512      // threads per CTA (both kernels)

// Scratch for attention partials (allocation-free: __device__ globals)
__device__ float g_m[BB * CHUNKS];
__device__ float g_s[BB * CHUNKS];
__device__ float g_acc[BB * CHUNKS * HH];

// ---------------------------------------------------------------------------
// Kernel 1: per-(batch, chunk) partial attention with online-softmax partials.
// One CTA = 256 weight indices of one batch. Bulk-loads 257 rows of
// encoder_output into SMEM (coalesced, high MLP), then computes everything
// out of SMEM.
// ---------------------------------------------------------------------------
__global__ __launch_bounds__(NT) void attn_partial(
    const float* __restrict__ enc,   // (B, W, H)
    const float* __restrict__ h0,    // (2, B, H)
    const float* __restrict__ c0,    // (2, B, H)
    const float* __restrict__ attW,  // (1, 2H)
    const float* __restrict__ attb)  // (1,)
{
    extern __shared__ float sm[];
    float* enc_s = sm;                   // (WC+1) * HH floats  (row j = global row r0-1+j)
    float* sc    = sm + (WC + 1) * HH;   // 260 scores / probs
    float* red   = sc + 260;             // 16-entry reduce scratch

    const int b = blockIdx.y, c = blockIdx.x;
    const int t = threadIdx.x, lane = t & 31, wrp = t >> 5;
    const int r0 = c * WC;

    // ---- scalar bias term: att_state[b] . wa_st + att_b ----
    float tb = 0.f;
    if (t < HH) {
        float hv = h0[(BB + b) * HH + t];   // layer 1 (last)
        float cv = c0[(BB + b) * HH + t];
        tb = hv * cv * attW[HH + t];
    }
    #pragma unroll
    for (int o = 16; o > 0; o >>= 1) tb += __shfl_xor_sync(0xffffffffu, tb, o);
    if (lane == 0) red[wrp] = tb;

    // ---- phase A0: bulk coalesced copy, 257 rows * 32 float4 = 8224 float4 ----
    {
        const float4* encv = reinterpret_cast<const float4*>(enc) + (long)b * WW * 32;
        float4* dst = reinterpret_cast<float4*>(enc_s);
        const int base = (r0 - 1) * 32;          // float4 index of row r0-1
        #pragma unroll
        for (int q = t; q < (WC + 1) * 32; q += NT) {
            const int gq = base + q;
            float4 v = make_float4(0.f, 0.f, 0.f, 0.f);
            if (gq >= 0) v = encv[gq];           // only row -1 (c==0) zero-filled
            dst[q] = v;
        }
    }
    __syncthreads();

    float tbias = attb[0];
    #pragma unroll
    for (int g = 0; g < 16; ++g) tbias += red[g];

    // ---- phase A1: scores from SMEM, warp-per-row ----
    const float4 wa = reinterpret_cast<const float4*>(attW)[lane];
    const float4* es = reinterpret_cast<const float4*>(enc_s);
    for (int j = wrp; j < WC; j += 16) {
        float4 e = es[j * 32 + lane];
        float d = e.x * wa.x + e.y * wa.y + e.z * wa.z + e.w * wa.w;
        #pragma unroll
        for (int o = 16; o > 0; o >>= 1) d += __shfl_xor_sync(0xffffffffu, d, o);
        if (lane == 0) sc[j] = d + tbias;
    }
    __syncthreads();

    // ---- local softmax over the 256 logits of this chunk ----
    // weight index w = r0 + t uses score of row w-1 (= sc[t]); w==0 -> logit 0
    float l = -INFINITY;
    if (t < WC) {
        l = sc[t];
        if (r0 + t == 0) l = 0.f;
    }
    float m = l;
    #pragma unroll
    for (int o = 16; o > 0; o >>= 1) m = fmaxf(m, __shfl_xor_sync(0xffffffffu, m, o));
    if (lane == 0) red[wrp] = m;
    __syncthreads();
    float M = red[0];
    #pragma unroll
    for (int g = 1; g < 16; ++g) M = fmaxf(M, red[g]);
    __syncthreads();                       // red reads done before reuse

    float p = (t < WC) ? __expf(l - M) : 0.f;
    if (t < WC) sc[t] = p;
    float s = p;
    #pragma unroll
    for (int o = 16; o > 0; o >>= 1) s += __shfl_xor_sync(0xffffffffu, s, o);
    if (lane == 0) red[wrp] = s;
    __syncthreads();                       // also publishes sc[] = p
    float S = 0.f;
    #pragma unroll
    for (int g = 0; g < 16; ++g) S += red[g];

    // ---- phase B: acc[h] = sum_i p[i] * enc[r0+i][h]  (SMEM row i+1) ----
    // warp w handles rows [w*16, w*16+16); lane = float4 column (conflict-free)
    float4 acc = make_float4(0.f, 0.f, 0.f, 0.f);
    #pragma unroll
    for (int i = wrp * 16; i < wrp * 16 + 16; ++i) {
        float pv = sc[i];                  // broadcast within warp
        float4 e = es[(i + 1) * 32 + lane];
        acc.x += pv * e.x; acc.y += pv * e.y; acc.z += pv * e.z; acc.w += pv * e.w;
    }
    __syncthreads();                       // enc_s reads done -> reuse as scratch
    float4* rbuf = reinterpret_cast<float4*>(enc_s);
    rbuf[wrp * 32 + lane] = acc;
    __syncthreads();
    if (wrp == 0) {
        float4 a = rbuf[lane];
        #pragma unroll
        for (int g = 1; g < 16; ++g) {
            float4 e = rbuf[g * 32 + lane];
            a.x += e.x; a.y += e.y; a.z += e.z; a.w += e.w;
        }
        reinterpret_cast<float4*>(g_acc + (b * CHUNKS + c) * HH)[lane] = a;
    }
    if (t == 0) { g_m[b * CHUNKS + c] = M; g_s[b * CHUNKS + c] = S; }
}

// ---------------------------------------------------------------------------
// Kernel 2: combine partials -> context x; input projection; 2 LSTM cells.
// One CTA per batch, 512 threads. All matmuls are WARP-PER-OUTPUT-ROW with
// lanes splitting K via float4 -> fully coalesced weight reads.
// ---------------------------------------------------------------------------
__device__ __forceinline__ float sigmoidf_(float v) {
    return 1.0f / (1.0f + __expf(-v));
}

__global__ __launch_bounds__(NT) void decode_tail(
    const float* __restrict__ input,  // (B, 1, I)
    const float* __restrict__ h0,     // (2, B, H)
    const float* __restrict__ c0,     // (2, B, H)
    const float* __restrict__ inpW,   // (I, 2H)
    const float* __restrict__ inpb,   // (I,)
    const float* __restrict__ Wih0, const float* __restrict__ Whh0,
    const float* __restrict__ bih0, const float* __restrict__ bhh0,
    const float* __restrict__ Wih1, const float* __restrict__ Whh1,
    const float* __restrict__ bih1, const float* __restrict__ bhh1,
    float* __restrict__ out)          // [output(B,1,H) | h(2,B,H) | c(2,B,H)]
{
    __shared__ float xcat[2 * HH];          // [context x | input]
    __shared__ float xin[HH], hh[HH], gates[4 * HH];
    const int b = blockIdx.x, t = threadIdx.x, lane = t & 31, wrp = t >> 5;

    // ---- combine chunk partials (log-sum-exp merge) ----
    if (t < HH) {
        float M = -INFINITY;
        #pragma unroll
        for (int c = 0; c < CHUNKS; ++c) M = fmaxf(M, g_m[b * CHUNKS + c]);
        float S = 0.f, a = 0.f;
        #pragma unroll
        for (int c = 0; c < CHUNKS; ++c) {
            float e = __expf(g_m[b * CHUNKS + c] - M);
            S += g_s[b * CHUNKS + c] * e;
            a += g_acc[(b * CHUNKS + c) * HH + t] * e;
        }
        xcat[t] = a / S;
        xcat[HH + t] = input[b * HH + t];
        hh[t] = h0[b * HH + t];             // layer 0 hidden
    }
    __syncthreads();

    // ---- xin = [x, input] @ inp_W.T + inp_b : warp-per-row (8 rows/warp) ----
    {
        const float4* xc = reinterpret_cast<const float4*>(xcat);
        for (int r = wrp; r < HH; r += 16) {
            const float4* wrow = reinterpret_cast<const float4*>(inpW + r * (2 * HH));
            float4 w0 = wrow[lane], w1 = wrow[32 + lane];
            float4 a0 = xc[lane],  a1 = xc[32 + lane];
            float d = w0.x * a0.x + w0.y * a0.y + w0.z * a0.z + w0.w * a0.w
                    + w1.x * a1.x + w1.y * a1.y + w1.z * a1.z + w1.w * a1.w;
            #pragma unroll
            for (int o = 16; o > 0; o >>= 1) d += __shfl_xor_sync(0xffffffffu, d, o);
            if (lane == 0) xin[r] = d + inpb[r];
        }
    }
    __syncthreads();

    // ---- LSTM cell 0: 512 gates, warp-per-gate (32 gates/warp) ----
    {
        const float4* xv = reinterpret_cast<const float4*>(xin);
        const float4* hv = reinterpret_cast<const float4*>(hh);
        float4 xr = xv[lane], hr = hv[lane];
        for (int g = wrp; g < 4 * HH; g += 16) {
            float4 wi = reinterpret_cast<const float4*>(Wih0 + g * HH)[lane];
            float4 wh = reinterpret_cast<const float4*>(Whh0 + g * HH)[lane];
            float d = wi.x * xr.x + wi.y * xr.y + wi.z * xr.z + wi.w * xr.w
                    + wh.x * hr.x + wh.y * hr.y + wh.z * hr.z + wh.w * hr.w;
            #pragma unroll
            for (int o = 16; o > 0; o >>= 1) d += __shfl_xor_sync(0xffffffffu, d, o);
            if (lane == 0) gates[g] = d + bih0[g] + bhh0[g];
        }
    }
    __syncthreads();
    if (t < HH) {
        float ig = sigmoidf_(gates[t]);
        float fg = sigmoidf_(gates[HH + t]);
        float gg = tanhf(gates[2 * HH + t]);
        float og = sigmoidf_(gates[3 * HH + t]);
        float cn = fg * c0[b * HH + t] + ig * gg;
        float hn = og * tanhf(cn);
        xin[t] = hn;                                  // input to layer 1
        hh[t]  = h0[BB * HH + b * HH + t];            // layer 1 hidden
        out[8192 + b * HH + t] = hn;                  // h stack, layer 0
        out[8192 + 2 * BB * HH + b * HH + t] = cn;    // c stack, layer 0
    }
    __syncthreads();

    // ---- LSTM cell 1 ----
    {
        const float4* xv = reinterpret_cast<const float4*>(xin);
        const float4* hv = reinterpret_cast<const float4*>(hh);
        float4 xr = xv[lane], hr = hv[lane];
        for (int g = wrp; g < 4 * HH; g += 16) {
            float4 wi = reinterpret_cast<const float4*>(Wih1 + g * HH)[lane];
            float4 wh = reinterpret_cast<const float4*>(Whh1 + g * HH)[lane];
            float d = wi.x * xr.x + wi.y * xr.y + wi.z * xr.z + wi.w * xr.w
                    + wh.x * hr.x + wh.y * hr.y + wh.z * hr.z + wh.w * hr.w;
            #pragma unroll
            for (int o = 16; o > 0; o >>= 1) d += __shfl_xor_sync(0xffffffffu, d, o);
            if (lane == 0) gates[g] = d + bih1[g] + bhh1[g];
        }
    }
    __syncthreads();
    if (t < HH) {
        float ig = sigmoidf_(gates[t]);
        float fg = sigmoidf_(gates[HH + t]);
        float gg = tanhf(gates[2 * HH + t]);
        float og = sigmoidf_(gates[3 * HH + t]);
        float cn = fg * c0[BB * HH + b * HH + t] + ig * gg;
        float hn = og * tanhf(cn);
        out[b * HH + t] = hn;                                   // output (B,1,H)
        out[8192 + BB * HH + b * HH + t] = hn;                  // h stack, layer 1
        out[8192 + 2 * BB * HH + BB * HH + b * HH + t] = cn;    // c stack, layer 1
    }
}

// ---------------------------------------------------------------------------
extern "C" void kernel_launch(void* const* d_in, const int* in_sizes, int n_in,
                              void* d_out, int out_size) {
    const float* input = (const float*)d_in[0];
    const float* h0    = (const float*)d_in[1];
    const float* c0    = (const float*)d_in[2];
    const float* enc   = (const float*)d_in[3];
    const float* attW  = (const float*)d_in[4];
    const float* attb  = (const float*)d_in[5];
    const float* inpW  = (const float*)d_in[6];
    const float* inpb  = (const float*)d_in[7];
    const float* Wih0  = (const float*)d_in[8];
    const float* Whh0  = (const float*)d_in[9];
    const float* bih0  = (const float*)d_in[10];
    const float* bhh0  = (const float*)d_in[11];
    const float* Wih1  = (const float*)d_in[12];
    const float* Whh1  = (const float*)d_in[13];
    const float* bih1  = (const float*)d_in[14];
    const float* bhh1  = (const float*)d_in[15];
    float* out = (float*)d_out;

    const int smem = ((WC + 1) * HH + 260 + 16) * (int)sizeof(float);  // ~132.7 KB
    cudaFuncSetAttribute(attn_partial, cudaFuncAttributeMaxDynamicSharedMemorySize, smem);

    attn_partial<<<dim3(CHUNKS, BB), NT, smem>>>(enc, h0, c0, attW, attb);
    decode_tail<<<BB, NT>>>(input, h0, c0, inpW, inpb,
                            Wih0, Whh0, bih0, bhh0,
                            Wih1, Whh1, bih1, bhh1, out);
}